// round 9
// baseline (speedup 1.0000x reference)
#include <cuda_runtime.h>
#include <cstdint>

// MessagePassing: out[row[e]] += x[col[e]]  for e in [0, E)
// x: [N, 32] f32; edge_index: [2, E] int32. row = ei[0:E], col = ei[E:2E].
//
// Converged design (R1-R8): edge-parallel, 8 lanes per edge x 16B chunks,
// NC LDG.128 gather + red.global.add.v4.f32 scatter, no hot-path branches.
// Scatter measured at ~37.9us ~= the ~6300 B/cyc LTS chip cap for its
// ~423MB of L2 traffic. This round: replace cudaMemsetAsync with a tuned
// float4 zero kernel (memset cost the total ~0.7us more than a zero kernel).

#define D 32
#define U 4

__global__ __launch_bounds__(256) void mp_zero_kernel(
        float4* __restrict__ out, int n4) {
    int i = blockIdx.x * blockDim.x + threadIdx.x;
    if (i < n4) out[i] = make_float4(0.f, 0.f, 0.f, 0.f);
}

__device__ __forceinline__ void red_add_v4(float* dst, float4 v) {
    asm volatile("red.global.add.v4.f32 [%0], {%1, %2, %3, %4};"
                 :: "l"(dst), "f"(v.x), "f"(v.y), "f"(v.z), "f"(v.w)
                 : "memory");
}

// Handles full groups only: edges [0, ngroups*U). No branches in hot path.
__global__ __launch_bounds__(256) void mp_scatter_kernel(
        const float* __restrict__ x,
        const int* __restrict__ ei,
        float* __restrict__ out,
        int E, int ngroups) {
    int t = blockIdx.x * blockDim.x + threadIdx.x;
    int g = t >> 3;                 // edge-group id: edges [g*U, g*U+U)
    if (g >= ngroups) return;
    int chunk = (t & 7) << 2;       // float offset within the 32-float row
    int e0 = g * U;

    int4 rows = __ldg(reinterpret_cast<const int4*>(ei + e0));
    int4 cols = __ldg(reinterpret_cast<const int4*>(ei + E + e0));

    int r[U] = {rows.x, rows.y, rows.z, rows.w};
    int c[U] = {cols.x, cols.y, cols.z, cols.w};

    float4 v[U];
    #pragma unroll
    for (int i = 0; i < U; i++)
        v[i] = __ldg(reinterpret_cast<const float4*>(
                   x + (long long)c[i] * D + chunk));

    #pragma unroll
    for (int i = 0; i < U; i++)
        red_add_v4(out + (long long)r[i] * D + chunk, v[i]);
}

// Scalar tail for E % U != 0 (not hit for E = 1.6M; kept for generality).
__global__ void mp_tail_kernel(const float* __restrict__ x,
                               const int* __restrict__ ei,
                               float* __restrict__ out,
                               int Estart, int E) {
    int t = blockIdx.x * blockDim.x + threadIdx.x;
    int e = Estart + (t >> 3);
    if (e >= E) return;
    int chunk = (t & 7) << 2;
    int r = ei[e];
    int c = ei[E + e];
    float4 v = __ldg(reinterpret_cast<const float4*>(
                   x + (long long)c * D + chunk));
    red_add_v4(out + (long long)r * D + chunk, v);
}

extern "C" void kernel_launch(void* const* d_in, const int* in_sizes, int n_in,
                              void* d_out, int out_size) {
    const float* x = (const float*)d_in[0];
    const int* ei = (const int*)d_in[1];
    float* out = (float*)d_out;

    const int E = in_sizes[1] / 2;    // edge_index has 2*E elements
    const int n4 = out_size / 4;      // out: N*32 floats -> N*8 float4

    // 1) zero the output (harness poisons it with 0xAA): one float4/thread
    {
        int threads = 256;
        int blocks = (n4 + threads - 1) / threads;
        mp_zero_kernel<<<blocks, threads>>>((float4*)out, n4);
    }

    // 2) gather + vectorized scatter-add, U edges per 8-lane group
    {
        int ngroups = E / U;
        long long total = (long long)ngroups * 8;
        int threads = 256;
        int blocks = (int)((total + threads - 1) / threads);
        mp_scatter_kernel<<<blocks, threads>>>(x, ei, out, E, ngroups);

        int tail = E - ngroups * U;
        if (tail > 0)
            mp_tail_kernel<<<(tail * 8 + 255) / 256, 256>>>(x, ei, out,
                                                            ngroups * U, E);
    }
}